// round 7
// baseline (speedup 1.0000x reference)
#include <cuda_runtime.h>
#include <cstdint>

// SmallRNNModel — 2-layer tanh RNN, B=64, T=512, I=256, H=512, O=256.
// Round 6: crossbar-balanced 8n x 4b register blocking (f32x2), k-split 8,
// 384-thread CTAs, intra-CTA ksp reduce, hoisted pre loads, 2 grid barriers.

#define T_STEPS 512
#define HID     512
#define BATCH   64
#define NCTA    128      // 16 n-tiles x 8 k-slices, flat launch
#define KS      8        // global k-split
#define RTHREADS 384     // 3 GEMM groups x 128
#define NB      32768    // HID*BATCH
#define NBH     16384    // NB/2 (float2 elements)

// ---------------- static device scratch ------------------------------------
__device__ float g_pre[T_STEPS * NB];       // [t][n][b]  64 MB
__device__ float g_part[3 * KS * NB];       // [grp*8+ks][n][b]  3.1 MB
__device__ float g_h0T[NB];                 // [n][b]
__device__ float g_h1T[NB];                 // [n][b]
__device__ unsigned g_bar_count = 0;
__device__ volatile unsigned g_bar_gen = 0;

// ---------------- f32x2 helpers (bit-exact fp32) ---------------------------
__device__ __forceinline__ void upk2(uint64_t v, float& x, float& y) {
    asm("mov.b64 {%0,%1},%2;" : "=f"(x), "=f"(y) : "l"(v));
}
__device__ __forceinline__ uint64_t fma2(uint64_t a, uint64_t b, uint64_t c) {
    uint64_t d; asm("fma.rn.f32x2 %0,%1,%2,%3;" : "=l"(d) : "l"(a), "l"(b), "l"(c));
    return d;
}
__device__ __forceinline__ uint64_t add2(uint64_t a, uint64_t b) {
    uint64_t d; asm("add.rn.f32x2 %0,%1,%2;" : "=l"(d) : "l"(a), "l"(b));
    return d;
}

// ---------------- software grid barrier (128 flat CTAs) --------------------
__device__ __forceinline__ void grid_barrier() {
    __syncthreads();
    if (threadIdx.x == 0) {
        __threadfence();
        unsigned gen = g_bar_gen;
        if (atomicAdd(&g_bar_count, 1u) == NCTA - 1) {
            atomicExch(&g_bar_count, 0u);
            __threadfence();
            g_bar_gen = gen + 1u;
        } else {
            while (g_bar_gen == gen) { }
            __threadfence();
        }
    }
    __syncthreads();
}

// ---------------- input-projection GEMM (layer 0) ---------------------------
__global__ void __launch_bounds__(256)
pre_gemm_kernel(const float* __restrict__ x,
                const float* __restrict__ W,
                const float* __restrict__ b1,
                const float* __restrict__ b2)
{
    __shared__ float As[16][68];
    __shared__ float Bs[16][68];

    const int tid = threadIdx.x;
    const int nt  = blockIdx.x;
    const int mt  = blockIdx.y;
    const int n0  = (tid >> 4) << 2;
    const int m0  = (tid & 15) << 2;
    const int lm = tid >> 2;
    const int lk = (tid & 3) << 2;

    const int arow = (lm * 512 + mt) * 256;
    const float* wrow = W + (nt * 64 + lm) * 256;

    float acc[4][4] = {};
    for (int k0 = 0; k0 < 256; k0 += 16) {
        float4 av = *(const float4*)(x + arow + k0 + lk);
        float4 wv = *(const float4*)(wrow + k0 + lk);
        As[lk + 0][lm] = av.x; As[lk + 1][lm] = av.y;
        As[lk + 2][lm] = av.z; As[lk + 3][lm] = av.w;
        Bs[lk + 0][lm] = wv.x; Bs[lk + 1][lm] = wv.y;
        Bs[lk + 2][lm] = wv.z; Bs[lk + 3][lm] = wv.w;
        __syncthreads();
        #pragma unroll
        for (int kk = 0; kk < 16; kk++) {
            float4 a = *(const float4*)&As[kk][m0];
            float4 w = *(const float4*)&Bs[kk][n0];
            float am[4] = {a.x, a.y, a.z, a.w};
            float wn[4] = {w.x, w.y, w.z, w.w};
            #pragma unroll
            for (int i = 0; i < 4; i++)
                #pragma unroll
                for (int j = 0; j < 4; j++)
                    acc[i][j] += am[i] * wn[j];
        }
        __syncthreads();
    }

    const int nbase = nt * 64 + n0;
    #pragma unroll
    for (int c = 0; c < 4; c++) {
        float bs = b1[nbase + c] + b2[nbase + c];
        float4 o = make_float4(acc[0][c] + bs, acc[1][c] + bs,
                               acc[2][c] + bs, acc[3][c] + bs);
        *(float4*)&g_pre[mt * NB + (nbase + c) * 64 + m0] = o;   // [t][n][b]
    }
}

// ---------------- fused persistent two-layer recurrence ---------------------
// CTA (nt, ks): per GEMM matrix, n in [32nt,32nt+32), k in [64ks,64ks+64).
// 3 groups x 128 threads; thread = (ksp2, ng4, bg16): 8n x 4b x K32, f32x2.
__global__ void __launch_bounds__(RTHREADS, 1)
rnn_fused_kernel(const float* __restrict__ W_hh0,
                 const float* __restrict__ W_ih1,
                 const float* __restrict__ W_hh1,
                 const float* __restrict__ b_ih1,
                 const float* __restrict__ b_hh1)
{
    __shared__ float2 Wd[3][64][32];      // dup pairs {w,w}; 48 KB
    __shared__ float  hbuf[2][64][64];    // h0s, h1s; 32 KB; reused as ksp scratch
    __shared__ float2 red2[128];          // Gp partial for h1 combine

    const int tid = threadIdx.x;
    const int cta = blockIdx.x;
    const int nt  = cta >> 3;         // 0..15
    const int ks  = cta & 7;          // 0..7

    // ---- load weight slices (dup pairs, [k][n]) ----
    #pragma unroll
    for (int g = 0; g < 3; g++) {
        const float* Wsrc = (g == 0) ? W_hh0 : (g == 1) ? W_ih1 : W_hh1;
        for (int e = tid; e < 2048; e += RTHREADS) {
            int k = e & 63, n = e >> 6;
            float w = Wsrc[(nt * 32 + n) * 512 + ks * 64 + k];
            Wd[g][k][n] = make_float2(w, w);
        }
    }
    // zero initial hidden states (each CTA zeroes its 256-slice of each)
    {
        if (tid < 256)  g_h0T[cta * 256 + tid] = 0.0f;
        if (tid >= 128) g_h1T[cta * 256 + tid - 128] = 0.0f;
    }

    // ---- GEMM thread constants ----
    const int grp = tid >> 7;              // 0,1,2
    const int lt  = tid & 127;
    const int bg  = lt & 15;  const int b0 = bg * 4;
    const int ng  = (lt >> 4) & 3; const int n0 = ng * 8;
    const int ksp = lt >> 6;               // 0,1
    const float (*hs)[64] = (grp == 2) ? hbuf[1] : hbuf[0];
    const float2 (*wd)[32] = Wd[grp];
    const int sidx = (grp * 64 + (lt & 63)) * 16;   // scratch slot (16 u64)
    // partial store base: [(grp*8+ks)][n][b]
    float* pstore = g_part + (size_t)(grp * KS + ks) * NB + (nt * 32 + n0) * 64 + b0;

    // ---- P2 constants ----
    const int q = cta * 128 + (tid & 127);          // float2 element pair index
    const int qn = q >> 5;                           // n of this pair
    const float bias1 = b_ih1[qn] + b_hh1[qn];
    float2* h0T2 = (float2*)g_h0T;
    float2* h1T2 = (float2*)g_h1T;
    const float2* pre2  = (const float2*)g_pre;
    const float2* part2 = (const float2*)g_part;

    grid_barrier();

    for (int i = 0; i <= T_STEPS; i++) {
        // ---- stage h slices: rows [64ks,64ks+64) of [n][b] ----
        {
            const float4* s0 = (const float4*)(g_h0T + ks * 4096);
            const float4* s1 = (const float4*)(g_h1T + ks * 4096);
            float4* d0 = (float4*)hbuf[0];
            float4* d1 = (float4*)hbuf[1];
            #pragma unroll
            for (int r = 0; r < 3; r++) {       // 3*384 = 1152 >= 1024
                int idx = r * RTHREADS + tid;
                if (idx < 1024) { d0[idx] = s0[idx]; d1[idx] = s1[idx]; }
            }
        }
        __syncthreads();

        // ---- GEMM: 8n x 4b x K32 per thread ----
        uint64_t acc[2][8] = {};
        #pragma unroll 4
        for (int kk = 0; kk < 32; kk++) {
            int k = ksp * 32 + kk;
            ulonglong2 ap = *(const ulonglong2*)&hs[k][b0];
            const ulonglong2* wp = (const ulonglong2*)&wd[k][n0];
            ulonglong2 wA = wp[0], wB = wp[1], wC = wp[2], wD = wp[3];
            acc[0][0] = fma2(ap.x, wA.x, acc[0][0]);
            acc[1][0] = fma2(ap.y, wA.x, acc[1][0]);
            acc[0][1] = fma2(ap.x, wA.y, acc[0][1]);
            acc[1][1] = fma2(ap.y, wA.y, acc[1][1]);
            acc[0][2] = fma2(ap.x, wB.x, acc[0][2]);
            acc[1][2] = fma2(ap.y, wB.x, acc[1][2]);
            acc[0][3] = fma2(ap.x, wB.y, acc[0][3]);
            acc[1][3] = fma2(ap.y, wB.y, acc[1][3]);
            acc[0][4] = fma2(ap.x, wC.x, acc[0][4]);
            acc[1][4] = fma2(ap.y, wC.x, acc[1][4]);
            acc[0][5] = fma2(ap.x, wC.y, acc[0][5]);
            acc[1][5] = fma2(ap.y, wC.y, acc[1][5]);
            acc[0][6] = fma2(ap.x, wD.x, acc[0][6]);
            acc[1][6] = fma2(ap.y, wD.x, acc[1][6]);
            acc[0][7] = fma2(ap.x, wD.y, acc[0][7]);
            acc[1][7] = fma2(ap.y, wD.y, acc[1][7]);
        }

        // ---- intra-CTA ksp reduce through smem (reuses hbuf) ----
        __syncthreads();                     // everyone done reading h
        uint64_t* scr = (uint64_t*)hbuf;
        if (ksp == 1) {
            #pragma unroll
            for (int r = 0; r < 8; r++) {
                scr[sidx + r * 2 + 0] = acc[0][r];
                scr[sidx + r * 2 + 1] = acc[1][r];
            }
        }
        // hoisted pre load for P2 (independent of barrier)
        float2 preval = make_float2(0.f, 0.f);
        if (tid < 128 && i < T_STEPS) preval = pre2[i * NBH + q];
        __syncthreads();
        if (ksp == 0) {
            #pragma unroll
            for (int r = 0; r < 8; r++) {
                uint64_t a0 = add2(acc[0][r], scr[sidx + r * 2 + 0]);
                uint64_t a1 = add2(acc[1][r], scr[sidx + r * 2 + 1]);
                float x0, x1, x2, x3;
                upk2(a0, x0, x1); upk2(a1, x2, x3);
                *(float4*)(pstore + r * 64) = make_float4(x0, x1, x2, x3);
            }
        }

        grid_barrier();

        // ---- P2: reduce + tanh (float2 vectorized) ----
        if (tid < 128) {
            if (i < T_STEPS) {
                float2 s = preval;
                #pragma unroll
                for (int j = 0; j < KS; j++) {
                    float2 v = part2[j * NBH + q];
                    s.x += v.x; s.y += v.y;
                }
                h0T2[q] = make_float2(tanhf(s.x), tanhf(s.y));
            }
        } else if (tid < 256) {
            if (i >= 1) {
                float2 s = make_float2(bias1, bias1);
                #pragma unroll
                for (int j = 0; j < KS; j++) {
                    float2 v = part2[(KS + j) * NBH + q];
                    s.x += v.x; s.y += v.y;
                }
                red2[tid - 128] = s;
            }
        } else {
            if (i >= 1) {
                float2 s = make_float2(0.f, 0.f);
                #pragma unroll
                for (int j = 0; j < KS; j++) {
                    float2 v = part2[(2 * KS + j) * NBH + q];
                    s.x += v.x; s.y += v.y;
                }
                red2[tid - 256].x += 0.0f;   // no-op keep
                float2 gp;
                __syncthreads();
                gp = red2[tid - 256];
                h1T2[q] = make_float2(tanhf(gp.x + s.x), tanhf(gp.y + s.y));
            } else {
                __syncthreads();
            }
        }
        if (tid < 256) __syncthreads();      // match the G1 branch's sync

        grid_barrier();
    }
}

// ---------------- final FC ---------------------------------------------------
__global__ void __launch_bounds__(256)
fc_kernel(const float* __restrict__ Wfc, const float* __restrict__ bfc,
          float* __restrict__ out)
{
    int idx = blockIdx.x * 256 + threadIdx.x;
    int o = idx >> 6;
    int b = idx & 63;
    const float* wr = Wfc + o * 512;
    float s = bfc[o];
    #pragma unroll 8
    for (int h = 0; h < 512; h++)
        s += g_h1T[h * 64 + b] * __ldg(&wr[h]);
    out[b * 256 + o] = s;
}

// ---------------- launch ------------------------------------------------------
extern "C" void kernel_launch(void* const* d_in, const int* in_sizes, int n_in,
                              void* d_out, int out_size)
{
    const float* x     = (const float*)d_in[0];
    const float* W_ih0 = (const float*)d_in[1];
    const float* W_hh0 = (const float*)d_in[2];
    const float* b_ih0 = (const float*)d_in[3];
    const float* b_hh0 = (const float*)d_in[4];
    const float* W_ih1 = (const float*)d_in[5];
    const float* W_hh1 = (const float*)d_in[6];
    const float* b_ih1 = (const float*)d_in[7];
    const float* b_hh1 = (const float*)d_in[8];
    const float* W_fc  = (const float*)d_in[9];
    const float* b_fc  = (const float*)d_in[10];
    float* out = (float*)d_out;

    pre_gemm_kernel<<<dim3(8, 512), 256>>>(x, W_ih0, b_ih0, b_hh0);
    rnn_fused_kernel<<<NCTA, RTHREADS>>>(W_hh0, W_ih1, W_hh1, b_ih1, b_hh1);
    fc_kernel<<<64, 256>>>(W_fc, b_fc, out);
}

// round 8
// speedup vs baseline: 1.1909x; 1.1909x over previous
#include <cuda_runtime.h>
#include <cstdint>

// SmallRNNModel — 2-layer tanh RNN, B=64, T=512, I=256, H=512, O=256.
// Round 7: decoupled layer pipeline. One persistent kernel, 128 CTAs:
//   CTAs 0..63  (A): layer-0 recurrence, bulk-sync among themselves only.
//   CTAs 64..127(B): layer-1 (Gp = h0@W_ih1^T and G1 = h1@W_hh1^T), lags A,
//                    consumes h0 history gated by A's per-group mini-bar gens.
// Per side per iteration: 1 full 64-scope barrier + 1 8-scope mini-barrier.

#define T_STEPS 512
#define HID     512
#define BATCH   64
#define NB      32768          // HID*BATCH
#define NBH     16384          // NB/2 (float2)

// ---------------- static device scratch ------------------------------------
__device__ float g_pre[T_STEPS * NB];            // [t][n][b]      64 MB
__device__ float g_h0hist[(T_STEPS + 1) * NB];   // slot i+1 = h0[i]; slot0=0
__device__ float g_h1T[NB];                      // h1 state [n][b]
__device__ float g_partA[2 * 8 * NB];            // parity x ks x [n][b]
__device__ float g_partP[2 * 8 * NB];
__device__ float g_partG[2 * 8 * NB];

__device__ unsigned g_cntA = 0;  __device__ volatile unsigned g_genA = 0;
__device__ unsigned g_cntB = 0;  __device__ volatile unsigned g_genB = 0;
__device__ unsigned g_cntAg[8] = {}; __device__ volatile unsigned g_genAg[8] = {};
__device__ unsigned g_cntBg[8] = {}; __device__ volatile unsigned g_genBg[8] = {};

// ---------------- f32x2 helpers (bit-exact fp32) ---------------------------
__device__ __forceinline__ void upk2(uint64_t v, float& x, float& y) {
    asm("mov.b64 {%0,%1},%2;" : "=f"(x), "=f"(y) : "l"(v));
}
__device__ __forceinline__ uint64_t fma2(uint64_t a, uint64_t b, uint64_t c) {
    uint64_t d; asm("fma.rn.f32x2 %0,%1,%2,%3;" : "=l"(d) : "l"(a), "l"(b), "l"(c));
    return d;
}

// ---------------- barriers ---------------------------------------------------
__device__ __forceinline__ void sw_barrier(unsigned* cnt, volatile unsigned* gen,
                                           unsigned members) {
    __syncthreads();
    if (threadIdx.x == 0) {
        __threadfence();
        unsigned g = *gen;
        if (atomicAdd(cnt, 1u) == members - 1) {
            *cnt = 0;
            __threadfence();
            *gen = g + 1u;
        } else {
            while (*gen == g) { }
            __threadfence();
        }
    }
    __syncthreads();
}

// ---------------- shared GEMM pieces ----------------------------------------
// 4n x 4b x K64 per thread; h in smem [k][b], w dup pairs {w,w} in smem [k][n].
__device__ __forceinline__ void gemm64(const float (*__restrict__ h)[64],
                                       const float2 (*__restrict__ w)[64],
                                       int b0, int n0, uint64_t acc[2][4]) {
    #pragma unroll 8
    for (int k = 0; k < 64; k++) {
        ulonglong2 ap  = *(const ulonglong2*)&h[k][b0];
        ulonglong2 w01 = *(const ulonglong2*)&w[k][n0];
        ulonglong2 w23 = *(const ulonglong2*)&w[k][n0 + 2];
        acc[0][0] = fma2(ap.x, w01.x, acc[0][0]);
        acc[1][0] = fma2(ap.y, w01.x, acc[1][0]);
        acc[0][1] = fma2(ap.x, w01.y, acc[0][1]);
        acc[1][1] = fma2(ap.y, w01.y, acc[1][1]);
        acc[0][2] = fma2(ap.x, w23.x, acc[0][2]);
        acc[1][2] = fma2(ap.y, w23.x, acc[1][2]);
        acc[0][3] = fma2(ap.x, w23.y, acc[0][3]);
        acc[1][3] = fma2(ap.y, w23.y, acc[1][3]);
    }
}
__device__ __forceinline__ void store_part(float* dst, uint64_t acc[2][4]) {
    #pragma unroll
    for (int c = 0; c < 4; c++) {
        float x0, x1, x2, x3;
        upk2(acc[0][c], x0, x1);
        upk2(acc[1][c], x2, x3);
        *(float4*)(dst + c * 64) = make_float4(x0, x1, x2, x3);
    }
}

// ---------------- input-projection GEMM (layer 0) ---------------------------
__global__ void __launch_bounds__(256)
pre_gemm_kernel(const float* __restrict__ x,
                const float* __restrict__ W,
                const float* __restrict__ b1,
                const float* __restrict__ b2)
{
    __shared__ float As[16][68];
    __shared__ float Bs[16][68];

    const int tid = threadIdx.x;
    const int nt  = blockIdx.x;
    const int mt  = blockIdx.y;
    const int n0  = (tid >> 4) << 2;
    const int m0  = (tid & 15) << 2;
    const int lm = tid >> 2;
    const int lk = (tid & 3) << 2;

    const int arow = (lm * 512 + mt) * 256;
    const float* wrow = W + (nt * 64 + lm) * 256;

    float acc[4][4] = {};
    for (int k0 = 0; k0 < 256; k0 += 16) {
        float4 av = *(const float4*)(x + arow + k0 + lk);
        float4 wv = *(const float4*)(wrow + k0 + lk);
        As[lk + 0][lm] = av.x; As[lk + 1][lm] = av.y;
        As[lk + 2][lm] = av.z; As[lk + 3][lm] = av.w;
        Bs[lk + 0][lm] = wv.x; Bs[lk + 1][lm] = wv.y;
        Bs[lk + 2][lm] = wv.z; Bs[lk + 3][lm] = wv.w;
        __syncthreads();
        #pragma unroll
        for (int kk = 0; kk < 16; kk++) {
            float4 a = *(const float4*)&As[kk][m0];
            float4 w = *(const float4*)&Bs[kk][n0];
            float am[4] = {a.x, a.y, a.z, a.w};
            float wn[4] = {w.x, w.y, w.z, w.w};
            #pragma unroll
            for (int i = 0; i < 4; i++)
                #pragma unroll
                for (int j = 0; j < 4; j++)
                    acc[i][j] += am[i] * wn[j];
        }
        __syncthreads();
    }

    const int nbase = nt * 64 + n0;
    #pragma unroll
    for (int c = 0; c < 4; c++) {
        float bs = b1[nbase + c] + b2[nbase + c];
        float4 o = make_float4(acc[0][c] + bs, acc[1][c] + bs,
                               acc[2][c] + bs, acc[3][c] + bs);
        *(float4*)&g_pre[mt * NB + (nbase + c) * 64 + m0] = o;   // [t][n][b]
    }
}

// ---------------- pipelined two-layer recurrence -----------------------------
__global__ void __launch_bounds__(256, 1)
rnn_pipe_kernel(const float* __restrict__ W_hh0,
                const float* __restrict__ W_ih1,
                const float* __restrict__ W_hh1,
                const float* __restrict__ b_ih1,
                const float* __restrict__ b_hh1)
{
    extern __shared__ char smem_raw[];
    const int tid = threadIdx.x;
    const int cta = blockIdx.x;
    const int b0  = (tid & 15) * 4;
    const int n0  = (tid >> 4) * 4;

    if (cta < 64) {
        // ================= A side: layer 0 =================
        float2 (*Wd)[64] = (float2(*)[64])smem_raw;             // 32 KB
        float  (*hA)[64] = (float(*)[64])(smem_raw + 32768);    // 16 KB
        const int nt = cta & 7;
        const int ks = cta >> 3;

        for (int e = tid; e < 4096; e += 256) {
            int n = e & 63, k = e >> 6;
            float w = W_hh0[(nt * 64 + n) * 512 + ks * 64 + k];
            Wd[k][n] = make_float2(w, w);
        }
        ((float2*)g_h0hist)[cta * 256 + tid] = make_float2(0.f, 0.f);  // slot 0

        const int q = cta * 256 + tid;                    // float2 index
        const float2* pre2 = (const float2*)g_pre;
        float2* hist2 = (float2*)g_h0hist;

        sw_barrier(&g_cntA, &g_genA, 64);

        for (int i = 0; i < T_STEPS; i++) {
            // stage h0[i-1]: rows [64ks..+64) of hist slot i
            {
                const float4* s = (const float4*)(g_h0hist + (size_t)i * NB + ks * 4096);
                float4* d = (float4*)hA;
                #pragma unroll
                for (int r = 0; r < 4; r++) d[tid + r * 256] = s[tid + r * 256];
            }
            __syncthreads();

            uint64_t acc[2][4] = {};
            gemm64(hA, Wd, b0, n0, acc);
            float* pb = g_partA + (size_t)(i & 1) * (8 * NB)
                      + (size_t)ks * NB + (nt * 64 + n0) * 64 + b0;
            store_part(pb, acc);

            sw_barrier(&g_cntA, &g_genA, 64);               // partials ready

            // P2: this thread owns pair q (n = q>>5 in group ks's row range)
            const float2* pA2 = (const float2*)(g_partA + (size_t)(i & 1) * (8 * NB));
            float2 s = pre2[(size_t)i * NBH + q];
            #pragma unroll
            for (int j = 0; j < 8; j++) {
                float2 v = pA2[j * NBH + q];
                s.x += v.x; s.y += v.y;
            }
            hist2[(size_t)(i + 1) * NBH + q] = make_float2(tanhf(s.x), tanhf(s.y));

            // group mini-barrier: rows [64ks..) now complete -> genAg[ks] = i+1
            sw_barrier(&g_cntAg[ks], &g_genAg[ks], 8);
        }
    } else {
        // ================= B side: layer 1 =================
        float2 (*WdP)[64] = (float2(*)[64])smem_raw;                  // 32 KB
        float2 (*WdG)[64] = (float2(*)[64])(smem_raw + 32768);        // 32 KB
        float  (*h0B)[64] = (float(*)[64])(smem_raw + 65536);         // 16 KB
        float  (*h1B)[64] = (float(*)[64])(smem_raw + 81920);         // 16 KB
        const int bid = cta - 64;
        const int nt = bid & 7;
        const int ks = bid >> 3;

        for (int e = tid; e < 4096; e += 256) {
            int n = e & 63, k = e >> 6;
            int gi = (nt * 64 + n) * 512 + ks * 64 + k;
            float wp = W_ih1[gi], wg = W_hh1[gi];
            WdP[k][n] = make_float2(wp, wp);
            WdG[k][n] = make_float2(wg, wg);
        }
        ((float2*)g_h1T)[bid * 256 + tid] = make_float2(0.f, 0.f);

        const int q  = bid * 256 + tid;
        const int qn = q >> 5;
        const float bias1 = b_ih1[qn] + b_hh1[qn];
        float2* h1T2 = (float2*)g_h1T;

        sw_barrier(&g_cntB, &g_genB, 64);

        for (int j = 0; j < T_STEPS; j++) {
            // wait until A's group ks has published h0[j] (genAg[ks] >= j+1)
            if (tid == 0) {
                while (g_genAg[ks] < (unsigned)(j + 1)) { }
                __threadfence();
            }
            __syncthreads();

            // stage h0[j] (hist slot j+1) and h1[j-1], rows [64ks..+64)
            {
                const float4* s0 = (const float4*)(g_h0hist + (size_t)(j + 1) * NB + ks * 4096);
                const float4* s1 = (const float4*)(g_h1T + ks * 4096);
                float4* d0 = (float4*)h0B;
                float4* d1 = (float4*)h1B;
                #pragma unroll
                for (int r = 0; r < 4; r++) {
                    d0[tid + r * 256] = s0[tid + r * 256];
                    d1[tid + r * 256] = s1[tid + r * 256];
                }
            }
            __syncthreads();

            uint64_t accP[2][4] = {}, accG[2][4] = {};
            gemm64(h0B, WdP, b0, n0, accP);
            gemm64(h1B, WdG, b0, n0, accG);
            const size_t par = (size_t)(j & 1) * (8 * NB);
            const size_t ofs = (size_t)ks * NB + (nt * 64 + n0) * 64 + b0;
            store_part(g_partP + par + ofs, accP);
            store_part(g_partG + par + ofs, accG);

            sw_barrier(&g_cntB, &g_genB, 64);               // partials ready

            const float2* pP2 = (const float2*)(g_partP + par);
            const float2* pG2 = (const float2*)(g_partG + par);
            float2 s = make_float2(bias1, bias1);
            #pragma unroll
            for (int kj = 0; kj < 8; kj++) {
                float2 u = pP2[kj * NBH + q];
                float2 v = pG2[kj * NBH + q];
                s.x += u.x + v.x;
                s.y += u.y + v.y;
            }
            h1T2[q] = make_float2(tanhf(s.x), tanhf(s.y));

            sw_barrier(&g_cntBg[ks], &g_genBg[ks], 8);      // h1 rows ready
        }
    }
}

// ---------------- final FC ---------------------------------------------------
__global__ void __launch_bounds__(256)
fc_kernel(const float* __restrict__ Wfc, const float* __restrict__ bfc,
          float* __restrict__ out)
{
    int idx = blockIdx.x * 256 + threadIdx.x;
    int o = idx >> 6;
    int b = idx & 63;
    const float* wr = Wfc + o * 512;
    float s = bfc[o];
    #pragma unroll 8
    for (int h = 0; h < 512; h++)
        s += g_h1T[h * 64 + b] * __ldg(&wr[h]);
    out[b * 256 + o] = s;
}

// ---------------- launch ------------------------------------------------------
extern "C" void kernel_launch(void* const* d_in, const int* in_sizes, int n_in,
                              void* d_out, int out_size)
{
    const float* x     = (const float*)d_in[0];
    const float* W_ih0 = (const float*)d_in[1];
    const float* W_hh0 = (const float*)d_in[2];
    const float* b_ih0 = (const float*)d_in[3];
    const float* b_hh0 = (const float*)d_in[4];
    const float* W_ih1 = (const float*)d_in[5];
    const float* W_hh1 = (const float*)d_in[6];
    const float* b_ih1 = (const float*)d_in[7];
    const float* b_hh1 = (const float*)d_in[8];
    const float* W_fc  = (const float*)d_in[9];
    const float* b_fc  = (const float*)d_in[10];
    float* out = (float*)d_out;

    static int smem_set = 0;
    if (!smem_set) {
        cudaFuncSetAttribute(rnn_pipe_kernel,
                             cudaFuncAttributeMaxDynamicSharedMemorySize, 98304);
        smem_set = 1;
    }

    pre_gemm_kernel<<<dim3(8, 512), 256>>>(x, W_ih0, b_ih0, b_hh0);
    rnn_pipe_kernel<<<128, 256, 98304>>>(W_hh0, W_ih1, W_hh1, b_ih1, b_hh1);
    fc_kernel<<<64, 256>>>(W_fc, b_fc, out);
}